// round 10
// baseline (speedup 1.0000x reference)
#include <cuda_runtime.h>

#define NB 32
#define NC 256
#define NH 64
#define NW 64
#define NM 16
#define EPSV 1e-5f

// Scratch (allocation-free rule: __device__ globals)
__device__ __align__(16) float g_xh[NB*NC*NH];        // mean over w: (b,c,h)
__device__ __align__(16) float g_xw[NB*NC*NW];        // mean over h: (b,c,w)
__device__ __align__(16) float g_pooled[NB*NC];       // mean over (h,w)
__device__ __align__(16) float g_part[NB*32*NH*NW];   // per-chunk channel partial sums
__device__ __align__(16) float g_fch[NB*NC];
__device__ __align__(16) float g_fsa[NB*NH*NW];
__device__ __align__(16) float g_sh[NB*NC*NH];
__device__ __align__(16) float g_sw[NB*NC*NW];

// Pass 1: one block per (b, chunk of 8 channels). Flattened 32-quarter loop
// with a 4-deep rolling prefetch buffer (16 regs instead of 32 for double
// buffer) to fit 4 CTAs/SM. __ldcg keeps x resident in L2 for pass 2.
__global__ __launch_bounds__(256, 4) void k_reduce(const float* __restrict__ x) {
    int b = blockIdx.y, chunk = blockIdx.x, t = threadIdx.x;
    int lane = t & 31, warp = t >> 5;
    __shared__ float s_row[8][1024];     // 32KB: per-thread-quarter row partials
    __shared__ float4 s_col[8][8][16];   // 8KB: [ci][warp][wquad]
    float4 ch[4];                        // cross-channel pixel sums per quarter
#pragma unroll
    for (int i = 0; i < 4; i++) ch[i] = make_float4(0.f, 0.f, 0.f, 0.f);

    const float4* base = (const float4*)x + ((size_t)b * NC + chunk * 8) * 1024;
    float4 buf[4];                       // rolling prefetch, 4 loads in flight
#pragma unroll
    for (int i = 0; i < 4; i++) buf[i] = __ldcg(base + i * 256 + t);

    float4 ca = make_float4(0.f, 0.f, 0.f, 0.f);
#pragma unroll
    for (int qi = 0; qi < 32; qi++) {
        int i = qi & 3;                  // quarter within channel
        int ci = qi >> 2;                // channel index
        float4 v = buf[i];
        if (qi < 28) buf[i] = __ldcg(base + (qi + 4) * 256 + t);
        ch[i].x += v.x; ch[i].y += v.y; ch[i].z += v.z; ch[i].w += v.w;
        ca.x += v.x; ca.y += v.y; ca.z += v.z; ca.w += v.w;
        float rs = (v.x + v.y) + (v.z + v.w);
        int q = i * 256 + t;
        // logical (row=q>>4, col=q&15) stored swizzled: col ^ (row&15)
        s_row[ci][(q & 0x3F0) | ((q ^ (q >> 4)) & 15)] = rs;
        if (i == 3) {
            // fold the two 16-lane halves (4 independent SHFLs, no chain)
            ca.x += __shfl_xor_sync(0xffffffffu, ca.x, 16);
            ca.y += __shfl_xor_sync(0xffffffffu, ca.y, 16);
            ca.z += __shfl_xor_sync(0xffffffffu, ca.z, 16);
            ca.w += __shfl_xor_sync(0xffffffffu, ca.w, 16);
            if (lane < 16) s_col[ci][warp][lane] = ca;
            ca = make_float4(0.f, 0.f, 0.f, 0.f);
        }
    }
    __syncthreads();

    // Tail A: row sums — 512 (ci,row) pairs, 2 per thread, swizzled reads
#pragma unroll
    for (int r2 = 0; r2 < 2; r2++) {
        int p = r2 * 256 + t;
        int ci = p >> 6, row = p & 63;
        const float* sr = s_row[ci] + row * 16;
        float s = 0.f;
#pragma unroll
        for (int k = 0; k < 16; k++) s += sr[(k ^ row) & 15];
        g_xh[((size_t)b * NC + chunk * 8 + ci) * NH + row] = s * (1.f / NW);
    }

    // Tail B: column sums + pooled — threads 0..127 = (ci, wquad)
    if (t < 128) {
        int ci = t >> 4, wq = t & 15;
        float4 s = s_col[ci][0][wq];
#pragma unroll
        for (int wv = 1; wv < 8; wv++) {
            float4 p = s_col[ci][wv][wq];
            s.x += p.x; s.y += p.y; s.z += p.z; s.w += p.w;
        }
        int c = chunk * 8 + ci;
        ((float4*)g_xw)[((size_t)b * NC + c) * 16 + wq] =
            make_float4(s.x * (1.f / NH), s.y * (1.f / NH),
                        s.z * (1.f / NH), s.w * (1.f / NH));
        float tot = s.x + s.y + s.z + s.w;       // reduce the 16 wq lanes
        tot += __shfl_xor_sync(0xffffffffu, tot, 8);
        tot += __shfl_xor_sync(0xffffffffu, tot, 4);
        tot += __shfl_xor_sync(0xffffffffu, tot, 2);
        tot += __shfl_xor_sync(0xffffffffu, tot, 1);
        if (wq == 0) g_pooled[b * NC + c] = tot * (1.f / (NH * NW));
    }

    // channel-partial store (plain float4, no atomics)
    float4* pp = (float4*)g_part + ((size_t)b * 32 + chunk) * 1024;
#pragma unroll
    for (int i = 0; i < 4; i++) pp[i * 256 + t] = ch[i];
}

// Fused middle kernel, 128 threads:
//  blocks [0,128):   attention MLP, block = (b, l-group of 32)
//  blocks [128,384): f_sa — sum 32 chunk-partials (w/ halo rows) + 3x3 conv + sigmoid
//  blocks [384,416): f_ch — 5-tap conv over pooled channels, one block per b
__global__ __launch_bounds__(128) void k_mid(
    const float* __restrict__ w10, const float* __restrict__ w11,
    const float* __restrict__ gamma, const float* __restrict__ beta,
    const float* __restrict__ mean, const float* __restrict__ var,
    const float* __restrict__ w20, const float* __restrict__ w21) {
    int bx = blockIdx.x, t = threadIdx.x;

    if (bx < 128) {
        __shared__ float s_w10t[NC * NM];  // transposed: [c][m]
        __shared__ float s_w11[NC * NM];   // [c][m]
        __shared__ float s_y[NM * 32];     // [m][lsub]
        __shared__ float s_inv[NM], s_bias[NM];
        int b = bx >> 2, lg = bx & 3;
        int lsub = t & 31, grp = t >> 5;
        int l = lg * 32 + lsub;
#pragma unroll
        for (int k = 0; k < 32; k++) {
            int idx = k * 128 + t;
            int m = idx >> 8, c = idx & 255;
            s_w10t[c * NM + m] = w10[idx];
            s_w11[idx] = w11[idx];
        }
        if (t < NM) {
            float inv = rsqrtf(var[t] + EPSV) * gamma[t];
            s_inv[t] = inv;
            s_bias[t] = beta[t] - mean[t] * inv;
        }
        __syncthreads();

        const float* catp = (l < 64) ? g_xh + (size_t)b * NC * 64 + l
                                     : g_xw + (size_t)b * NC * 64 + (l - 64);
        float a0 = 0.f, a1 = 0.f, a2 = 0.f, a3 = 0.f;
#pragma unroll 16
        for (int c = 0; c < NC; c++) {
            float cv = __ldg(catp + (size_t)c * 64);
            float4 wv = *(const float4*)&s_w10t[c * NM + grp * 4];
            a0 = fmaf(wv.x, cv, a0);
            a1 = fmaf(wv.y, cv, a1);
            a2 = fmaf(wv.z, cv, a2);
            a3 = fmaf(wv.w, cv, a3);
        }
        int m0 = grp * 4;
        s_y[(m0 + 0) * 32 + lsub] = fmaxf(fmaf(a0, s_inv[m0 + 0], s_bias[m0 + 0]), 0.f);
        s_y[(m0 + 1) * 32 + lsub] = fmaxf(fmaf(a1, s_inv[m0 + 1], s_bias[m0 + 1]), 0.f);
        s_y[(m0 + 2) * 32 + lsub] = fmaxf(fmaf(a2, s_inv[m0 + 2], s_bias[m0 + 2]), 0.f);
        s_y[(m0 + 3) * 32 + lsub] = fmaxf(fmaf(a3, s_inv[m0 + 3], s_bias[m0 + 3]), 0.f);
        __syncthreads();

        float yr[NM];
#pragma unroll
        for (int m = 0; m < NM; m++) yr[m] = s_y[m * 32 + lsub];
        float* dst = (l < 64) ? g_sh + (size_t)b * NC * 64 + l
                              : g_sw + (size_t)b * NC * 64 + (l - 64);
#pragma unroll 4
        for (int it = 0; it < 64; it++) {
            int c = it * 4 + grp;
            const float4* wr = (const float4*)&s_w11[c * NM];
            float4 w0 = wr[0], w1 = wr[1], w2 = wr[2], w3 = wr[3];
            float ae = 0.f, ao = 0.f;                 // dual chains
            ae = fmaf(w0.x, yr[0], ae);  ao = fmaf(w0.y, yr[1], ao);
            ae = fmaf(w0.z, yr[2], ae);  ao = fmaf(w0.w, yr[3], ao);
            ae = fmaf(w1.x, yr[4], ae);  ao = fmaf(w1.y, yr[5], ao);
            ae = fmaf(w1.z, yr[6], ae);  ao = fmaf(w1.w, yr[7], ao);
            ae = fmaf(w2.x, yr[8], ae);  ao = fmaf(w2.y, yr[9], ao);
            ae = fmaf(w2.z, yr[10], ae); ao = fmaf(w2.w, yr[11], ao);
            ae = fmaf(w3.x, yr[12], ae); ao = fmaf(w3.y, yr[13], ao);
            ae = fmaf(w3.z, yr[14], ae); ao = fmaf(w3.w, yr[15], ao);
            float a = ae + ao;
            dst[(size_t)c * 64] = 1.f / (1.f + __expf(-a));
        }
    } else if (bx < 384) {
        // f_sa tile: 8 output rows per block, halo rows h0-1..h0+8 in smem
        __shared__ __align__(16) float s_m[10][64];
        int idx = bx - 128;
        int b = idx >> 3, tile = idx & 7;
        int h0 = tile * 8;
        const float4* pb = (const float4*)g_part + (size_t)b * 32 * 1024;
        // fill 10 rows x 16 quads = 160 quads, summing 32 chunk-partials each
        for (int qi = t; qi < 160; qi += 128) {
            int lr = qi >> 4, wq = qi & 15;
            int hh = h0 - 1 + lr;
            float4 acc = make_float4(0.f, 0.f, 0.f, 0.f);
            if (hh >= 0 && hh < NH) {
                int poff = hh * 16 + wq;
#pragma unroll 8
                for (int ck = 0; ck < 32; ck++) {
                    float4 v = __ldg(pb + ck * 1024 + poff);
                    acc.x += v.x; acc.y += v.y; acc.z += v.z; acc.w += v.w;
                }
            }
            *(float4*)&s_m[lr][wq * 4] =
                make_float4(acc.x * (1.f / NC), acc.y * (1.f / NC),
                            acc.z * (1.f / NC), acc.w * (1.f / NC));
        }
        float kk[9];
#pragma unroll
        for (int i = 0; i < 9; i++) kk[i] = w21[i];
        __syncthreads();
        // conv: 128 quads = 8 rows x 16 quads
        int lr = (t >> 4) + 1;         // smem row for output row h0 + (t>>4)
        int w0 = (t & 15) * 4;
        float4 o;
        float* op = (float*)&o;
#pragma unroll
        for (int j = 0; j < 4; j++) {
            int w = w0 + j;
            float acc = 0.f;
#pragma unroll
            for (int dh = -1; dh <= 1; dh++) {
#pragma unroll
                for (int dw = -1; dw <= 1; dw++) {
                    int ww = w + dw;
                    if (ww >= 0 && ww < NW)
                        acc += s_m[lr + dh][ww] * kk[(dh + 1) * 3 + (dw + 1)];
                }
            }
            op[j] = 1.f / (1.f + __expf(-acc));
        }
        ((float4*)g_fsa)[(size_t)b * 1024 + (h0 + (t >> 4)) * 16 + (t & 15)] = o;
    } else {
        // f_ch: 5-tap SAME conv over pooled channels, block per b
        int b = bx - 384;
#pragma unroll
        for (int r = 0; r < 2; r++) {
            int cc = r * 128 + t;
            float acc = 0.f;
#pragma unroll
            for (int k = 0; k < 5; k++) {
                int c2 = cc + k - 2;
                if (c2 >= 0 && c2 < NC)
                    acc += __ldg(&g_pooled[b * NC + c2]) * w20[k];
            }
            g_fch[b * NC + cc] = acc;
        }
    }
}

// Pass 2: out = x * (f_ch + s_h*s_w + f_sa). One block per (b, c-pair).
// Block mapping is REVERSED vs pass 1's read order so the first blocks hit the
// most-recently-cached tail of x in L2 (telescoping reuse); __ldcg keeps x
// resident for the next graph replay's forward pass.
__global__ __launch_bounds__(256) void k_final(const float* __restrict__ x,
                                               float* __restrict__ out) {
    int b = NB - 1 - (int)blockIdx.y;
    int cp = NC / 2 - 1 - (int)blockIdx.x;
    int t = threadIdx.x;
    int bc0 = b * NC + cp * 2;
    __shared__ __align__(16) float s_sh[2][64];
    __shared__ __align__(16) float s_sw[2][64];
    if (t < 64)       s_sh[0][t]       = g_sh[(size_t)bc0 * 64 + t];
    else if (t < 128) s_sh[1][t - 64]  = g_sh[(size_t)(bc0 + 1) * 64 + (t - 64)];
    else if (t < 192) s_sw[0][t - 128] = g_sw[(size_t)bc0 * 64 + (t - 128)];
    else              s_sw[1][t - 192] = g_sw[(size_t)(bc0 + 1) * 64 + (t - 192)];
    float fch0 = g_fch[bc0], fch1 = g_fch[bc0 + 1];
    __syncthreads();
    const float4* xp0 = (const float4*)x + (size_t)bc0 * 1024;
    const float4* xp1 = xp0 + 1024;
    float4* op0 = (float4*)out + (size_t)bc0 * 1024;
    float4* op1 = op0 + 1024;
    const float4* fp = (const float4*)g_fsa + (size_t)b * 1024;
#pragma unroll
    for (int i = 0; i < 4; i++) {
        int q = i * 256 + t;
        float4 x0 = __ldcg(xp0 + q);
        float4 x1 = __ldcg(xp1 + q);
        float4 fv = __ldg(fp + q);
        int r = q >> 4;
        float sh0 = s_sh[0][r], sh1 = s_sh[1][r];
        float4 sw0 = ((const float4*)s_sw[0])[q & 15];
        float4 sw1 = ((const float4*)s_sw[1])[q & 15];
        float4 o0, o1;
        o0.x = x0.x * (fch0 + sh0 * sw0.x + fv.x);
        o0.y = x0.y * (fch0 + sh0 * sw0.y + fv.y);
        o0.z = x0.z * (fch0 + sh0 * sw0.z + fv.z);
        o0.w = x0.w * (fch0 + sh0 * sw0.w + fv.w);
        o1.x = x1.x * (fch1 + sh1 * sw1.x + fv.x);
        o1.y = x1.y * (fch1 + sh1 * sw1.y + fv.y);
        o1.z = x1.z * (fch1 + sh1 * sw1.z + fv.z);
        o1.w = x1.w * (fch1 + sh1 * sw1.w + fv.w);
        __stcs(op0 + q, o0);
        __stcs(op1 + q, o1);
    }
}

extern "C" void kernel_launch(void* const* d_in, const int* in_sizes, int n_in,
                              void* d_out, int out_size) {
    const float* x     = (const float*)d_in[0];
    const float* w10   = (const float*)d_in[1];
    const float* w11   = (const float*)d_in[2];
    const float* gamma = (const float*)d_in[3];
    const float* beta  = (const float*)d_in[4];
    const float* mean  = (const float*)d_in[5];
    const float* var   = (const float*)d_in[6];
    const float* w20   = (const float*)d_in[7];
    const float* w21   = (const float*)d_in[8];
    float* out = (float*)d_out;

    k_reduce<<<dim3(32, NB), 256>>>(x);
    k_mid<<<416, 128>>>(w10, w11, gamma, beta, mean, var, w20, w21);
    k_final<<<dim3(NC / 2, NB), 256>>>(x, out);
}

// round 12
// speedup vs baseline: 1.0166x; 1.0166x over previous
#include <cuda_runtime.h>

#define NB 32
#define NC 256
#define NH 64
#define NW 64
#define NM 16
#define EPSV 1e-5f

// Scratch (allocation-free rule: __device__ globals)
__device__ __align__(16) float g_xh[NB*NC*NH];        // mean over w: (b,c,h)
__device__ __align__(16) float g_xw[NB*NC*NW];        // mean over h: (b,c,w)
__device__ __align__(16) float g_pooled[NB*NC];       // mean over (h,w)
__device__ __align__(16) float g_part[NB*32*NH*NW];   // per-chunk channel partial sums
__device__ __align__(16) float g_fch[NB*NC];
__device__ __align__(16) float g_fsa[NB*NH*NW];
__device__ __align__(16) float g_sh[NB*NC*NH];
__device__ __align__(16) float g_sw[NB*NC*NW];

// Pass 1 (R8 proven config): one block per (b, chunk of 8 channels).
// Double-buffered channel loads — whole next channel (4 LDG.128) in flight
// while current is consumed; no cross-lane ops in the hot loop.
__global__ __launch_bounds__(256, 3) void k_reduce(const float* __restrict__ x) {
    int b = blockIdx.y, chunk = blockIdx.x, t = threadIdx.x;
    int lane = t & 31, warp = t >> 5;
    __shared__ float s_row[8][1024];     // 32KB: per-thread-quarter row partials
    __shared__ float4 s_col[8][8][16];   // 16KB: [ci][warp][wquad]
    float4 ch[4];                        // cross-channel pixel sums per quarter
#pragma unroll
    for (int i = 0; i < 4; i++) ch[i] = make_float4(0.f, 0.f, 0.f, 0.f);

    const float4* base = (const float4*)x + ((size_t)b * NC + chunk * 8) * 1024;
    float4 buf[2][4];
#pragma unroll
    for (int i = 0; i < 4; i++) buf[0][i] = __ldcg(base + i * 256 + t);

#pragma unroll
    for (int ci = 0; ci < 8; ci++) {
        int cur = ci & 1;
        if (ci < 7) {
            const float4* pn = base + (size_t)(ci + 1) * 1024;
#pragma unroll
            for (int i = 0; i < 4; i++) buf[cur ^ 1][i] = __ldcg(pn + i * 256 + t);
        }
        float4 ca = make_float4(0.f, 0.f, 0.f, 0.f);
#pragma unroll
        for (int i = 0; i < 4; i++) {
            float4 v = buf[cur][i];
            ch[i].x += v.x; ch[i].y += v.y; ch[i].z += v.z; ch[i].w += v.w;
            ca.x += v.x; ca.y += v.y; ca.z += v.z; ca.w += v.w;
            float rs = (v.x + v.y) + (v.z + v.w);
            int q = i * 256 + t;
            // logical (row=q>>4, col=q&15) stored swizzled: col ^ (row&15)
            s_row[ci][(q & 0x3F0) | ((q ^ (q >> 4)) & 15)] = rs;
        }
        // fold the two 16-lane halves (4 independent SHFLs, no chain)
        ca.x += __shfl_xor_sync(0xffffffffu, ca.x, 16);
        ca.y += __shfl_xor_sync(0xffffffffu, ca.y, 16);
        ca.z += __shfl_xor_sync(0xffffffffu, ca.z, 16);
        ca.w += __shfl_xor_sync(0xffffffffu, ca.w, 16);
        if (lane < 16) s_col[ci][warp][lane] = ca;
    }
    __syncthreads();

    // Tail A: row sums — 512 (ci,row) pairs, 2 per thread, swizzled reads
#pragma unroll
    for (int r2 = 0; r2 < 2; r2++) {
        int p = r2 * 256 + t;
        int ci = p >> 6, row = p & 63;
        const float* sr = s_row[ci] + row * 16;
        float s = 0.f;
#pragma unroll
        for (int k = 0; k < 16; k++) s += sr[(k ^ row) & 15];
        g_xh[((size_t)b * NC + chunk * 8 + ci) * NH + row] = s * (1.f / NW);
    }

    // Tail B: column sums + pooled — threads 0..127 = (ci, wquad)
    if (t < 128) {
        int ci = t >> 4, wq = t & 15;
        float4 s = s_col[ci][0][wq];
#pragma unroll
        for (int wv = 1; wv < 8; wv++) {
            float4 p = s_col[ci][wv][wq];
            s.x += p.x; s.y += p.y; s.z += p.z; s.w += p.w;
        }
        int c = chunk * 8 + ci;
        ((float4*)g_xw)[((size_t)b * NC + c) * 16 + wq] =
            make_float4(s.x * (1.f / NH), s.y * (1.f / NH),
                        s.z * (1.f / NH), s.w * (1.f / NH));
        float tot = s.x + s.y + s.z + s.w;       // reduce the 16 wq lanes
        tot += __shfl_xor_sync(0xffffffffu, tot, 8);
        tot += __shfl_xor_sync(0xffffffffu, tot, 4);
        tot += __shfl_xor_sync(0xffffffffu, tot, 2);
        tot += __shfl_xor_sync(0xffffffffu, tot, 1);
        if (wq == 0) g_pooled[b * NC + c] = tot * (1.f / (NH * NW));
    }

    // channel-partial store (plain float4, no atomics)
    float4* pp = (float4*)g_part + ((size_t)b * 32 + chunk) * 1024;
#pragma unroll
    for (int i = 0; i < 4; i++) pp[i * 256 + t] = ch[i];
}

// Fused middle kernel, 128 threads:
//  blocks [0,128):   attention MLP, block = (b, l-group of 32)
//  blocks [128,384): f_sa — sum 32 chunk-partials (w/ halo rows) + 3x3 conv + sigmoid
//  blocks [384,416): f_ch — 5-tap conv over pooled channels, one block per b
__global__ __launch_bounds__(128) void k_mid(
    const float* __restrict__ w10, const float* __restrict__ w11,
    const float* __restrict__ gamma, const float* __restrict__ beta,
    const float* __restrict__ mean, const float* __restrict__ var,
    const float* __restrict__ w20, const float* __restrict__ w21) {
    int bx = blockIdx.x, t = threadIdx.x;

    if (bx < 128) {
        __shared__ float s_w10t[NC * NM];  // transposed: [c][m]
        __shared__ float s_w11[NC * NM];   // [c][m]
        __shared__ float s_y[NM * 32];     // [m][lsub]
        __shared__ float s_inv[NM], s_bias[NM];
        int b = bx >> 2, lg = bx & 3;
        int lsub = t & 31, grp = t >> 5;
        int l = lg * 32 + lsub;
#pragma unroll
        for (int k = 0; k < 32; k++) {
            int idx = k * 128 + t;
            int m = idx >> 8, c = idx & 255;
            s_w10t[c * NM + m] = w10[idx];
            s_w11[idx] = w11[idx];
        }
        if (t < NM) {
            float inv = rsqrtf(var[t] + EPSV) * gamma[t];
            s_inv[t] = inv;
            s_bias[t] = beta[t] - mean[t] * inv;
        }
        __syncthreads();

        const float* catp = (l < 64) ? g_xh + (size_t)b * NC * 64 + l
                                     : g_xw + (size_t)b * NC * 64 + (l - 64);
        float a0 = 0.f, a1 = 0.f, a2 = 0.f, a3 = 0.f;
#pragma unroll 16
        for (int c = 0; c < NC; c++) {
            float cv = __ldg(catp + (size_t)c * 64);
            float4 wv = *(const float4*)&s_w10t[c * NM + grp * 4];
            a0 = fmaf(wv.x, cv, a0);
            a1 = fmaf(wv.y, cv, a1);
            a2 = fmaf(wv.z, cv, a2);
            a3 = fmaf(wv.w, cv, a3);
        }
        int m0 = grp * 4;
        s_y[(m0 + 0) * 32 + lsub] = fmaxf(fmaf(a0, s_inv[m0 + 0], s_bias[m0 + 0]), 0.f);
        s_y[(m0 + 1) * 32 + lsub] = fmaxf(fmaf(a1, s_inv[m0 + 1], s_bias[m0 + 1]), 0.f);
        s_y[(m0 + 2) * 32 + lsub] = fmaxf(fmaf(a2, s_inv[m0 + 2], s_bias[m0 + 2]), 0.f);
        s_y[(m0 + 3) * 32 + lsub] = fmaxf(fmaf(a3, s_inv[m0 + 3], s_bias[m0 + 3]), 0.f);
        __syncthreads();

        float yr[NM];
#pragma unroll
        for (int m = 0; m < NM; m++) yr[m] = s_y[m * 32 + lsub];
        float* dst = (l < 64) ? g_sh + (size_t)b * NC * 64 + l
                              : g_sw + (size_t)b * NC * 64 + (l - 64);
#pragma unroll 4
        for (int it = 0; it < 64; it++) {
            int c = it * 4 + grp;
            const float4* wr = (const float4*)&s_w11[c * NM];
            float4 w0 = wr[0], w1 = wr[1], w2 = wr[2], w3 = wr[3];
            float ae = 0.f, ao = 0.f;                 // dual chains
            ae = fmaf(w0.x, yr[0], ae);  ao = fmaf(w0.y, yr[1], ao);
            ae = fmaf(w0.z, yr[2], ae);  ao = fmaf(w0.w, yr[3], ao);
            ae = fmaf(w1.x, yr[4], ae);  ao = fmaf(w1.y, yr[5], ao);
            ae = fmaf(w1.z, yr[6], ae);  ao = fmaf(w1.w, yr[7], ao);
            ae = fmaf(w2.x, yr[8], ae);  ao = fmaf(w2.y, yr[9], ao);
            ae = fmaf(w2.z, yr[10], ae); ao = fmaf(w2.w, yr[11], ao);
            ae = fmaf(w3.x, yr[12], ae); ao = fmaf(w3.y, yr[13], ao);
            ae = fmaf(w3.z, yr[14], ae); ao = fmaf(w3.w, yr[15], ao);
            float a = ae + ao;
            dst[(size_t)c * 64] = 1.f / (1.f + __expf(-a));
        }
    } else if (bx < 384) {
        // f_sa tile: 8 output rows per block, halo rows h0-1..h0+8 in smem
        __shared__ __align__(16) float s_m[10][64];
        int idx = bx - 128;
        int b = idx >> 3, tile = idx & 7;
        int h0 = tile * 8;
        const float4* pb = (const float4*)g_part + (size_t)b * 32 * 1024;
        // fill 10 rows x 16 quads = 160 quads, summing 32 chunk-partials each
        for (int qi = t; qi < 160; qi += 128) {
            int lr = qi >> 4, wq = qi & 15;
            int hh = h0 - 1 + lr;
            float4 acc = make_float4(0.f, 0.f, 0.f, 0.f);
            if (hh >= 0 && hh < NH) {
                int poff = hh * 16 + wq;
#pragma unroll 8
                for (int ck = 0; ck < 32; ck++) {
                    float4 v = __ldg(pb + ck * 1024 + poff);
                    acc.x += v.x; acc.y += v.y; acc.z += v.z; acc.w += v.w;
                }
            }
            *(float4*)&s_m[lr][wq * 4] =
                make_float4(acc.x * (1.f / NC), acc.y * (1.f / NC),
                            acc.z * (1.f / NC), acc.w * (1.f / NC));
        }
        float kk[9];
#pragma unroll
        for (int i = 0; i < 9; i++) kk[i] = w21[i];
        __syncthreads();
        // conv: 128 quads = 8 rows x 16 quads
        int lr = (t >> 4) + 1;         // smem row for output row h0 + (t>>4)
        int w0 = (t & 15) * 4;
        float4 o;
        float* op = (float*)&o;
#pragma unroll
        for (int j = 0; j < 4; j++) {
            int w = w0 + j;
            float acc = 0.f;
#pragma unroll
            for (int dh = -1; dh <= 1; dh++) {
#pragma unroll
                for (int dw = -1; dw <= 1; dw++) {
                    int ww = w + dw;
                    if (ww >= 0 && ww < NW)
                        acc += s_m[lr + dh][ww] * kk[(dh + 1) * 3 + (dw + 1)];
                }
            }
            op[j] = 1.f / (1.f + __expf(-acc));
        }
        ((float4*)g_fsa)[(size_t)b * 1024 + (h0 + (t >> 4)) * 16 + (t & 15)] = o;
    } else {
        // f_ch: 5-tap SAME conv over pooled channels, block per b
        int b = bx - 384;
#pragma unroll
        for (int r = 0; r < 2; r++) {
            int cc = r * 128 + t;
            float acc = 0.f;
#pragma unroll
            for (int k = 0; k < 5; k++) {
                int c2 = cc + k - 2;
                if (c2 >= 0 && c2 < NC)
                    acc += __ldg(&g_pooled[b * NC + c2]) * w20[k];
            }
            g_fch[b * NC + cc] = acc;
        }
    }
}

// Pass 2: out = x * (f_ch + s_h*s_w + f_sa). One block per (b, 4-channel group)
// — f_sa float4 loaded once per pixel for 4 planes (L2/LTS traffic cut).
// Block mapping REVERSED vs pass 1's read order (L2 telescoping); __ldcg keeps
// x resident for the next graph replay's forward pass.
__global__ __launch_bounds__(256) void k_final(const float* __restrict__ x,
                                               float* __restrict__ out) {
    int b = NB - 1 - (int)blockIdx.y;
    int cg = NC / 4 - 1 - (int)blockIdx.x;
    int t = threadIdx.x;
    int bc0 = b * NC + cg * 4;
    __shared__ __align__(16) float s_sh[4][64];
    __shared__ __align__(16) float s_sw[4][64];
#pragma unroll
    for (int j = 0; j < 2; j++) {
        int p = j * 256 + t;
        int cc = p >> 6, hh = p & 63;
        if (cc < 4) s_sh[cc][hh] = g_sh[(size_t)(bc0 + cc) * 64 + hh];
        else        s_sw[cc - 4][hh] = g_sw[(size_t)(bc0 + cc - 4) * 64 + hh];
    }
    float fch[4];
#pragma unroll
    for (int c = 0; c < 4; c++) fch[c] = g_fch[bc0 + c];
    __syncthreads();
    const float4* xp = (const float4*)x + (size_t)bc0 * 1024;
    float4* op = (float4*)out + (size_t)bc0 * 1024;
    const float4* fp = (const float4*)g_fsa + (size_t)b * 1024;
#pragma unroll
    for (int i = 0; i < 4; i++) {
        int q = i * 256 + t;
        float4 fv = __ldg(fp + q);
        int r = q >> 4;
        float4 xv[4];
#pragma unroll
        for (int c = 0; c < 4; c++) xv[c] = __ldcg(xp + c * 1024 + q);
#pragma unroll
        for (int c = 0; c < 4; c++) {
            float sh = s_sh[c][r];
            float4 swv = ((const float4*)s_sw[c])[q & 15];
            float4 o;
            o.x = xv[c].x * (fch[c] + sh * swv.x + fv.x);
            o.y = xv[c].y * (fch[c] + sh * swv.y + fv.y);
            o.z = xv[c].z * (fch[c] + sh * swv.z + fv.z);
            o.w = xv[c].w * (fch[c] + sh * swv.w + fv.w);
            __stcs(op + c * 1024 + q, o);
        }
    }
}

extern "C" void kernel_launch(void* const* d_in, const int* in_sizes, int n_in,
                              void* d_out, int out_size) {
    const float* x     = (const float*)d_in[0];
    const float* w10   = (const float*)d_in[1];
    const float* w11   = (const float*)d_in[2];
    const float* gamma = (const float*)d_in[3];
    const float* beta  = (const float*)d_in[4];
    const float* mean  = (const float*)d_in[5];
    const float* var   = (const float*)d_in[6];
    const float* w20   = (const float*)d_in[7];
    const float* w21   = (const float*)d_in[8];
    float* out = (float*)d_out;

    k_reduce<<<dim3(32, NB), 256>>>(x);
    k_mid<<<416, 128>>>(w10, w11, gamma, beta, mean, var, w20, w21);
    k_final<<<dim3(NC / 4, NB), 256>>>(x, out);
}

// round 13
// speedup vs baseline: 1.0295x; 1.0127x over previous
#include <cuda_runtime.h>

#define NB 32
#define NC 256
#define NH 64
#define NW 64
#define NM 16
#define EPSV 1e-5f

// Scratch (allocation-free rule: __device__ globals)
__device__ __align__(16) float g_xh[NB*NC*NH];        // mean over w: (b,c,h)
__device__ __align__(16) float g_xw[NB*NC*NW];        // mean over h: (b,c,w)
__device__ __align__(16) float g_pooled[NB*NC];       // mean over (h,w)
__device__ __align__(16) float g_part[NB*32*NH*NW];   // per-chunk channel partial sums
__device__ __align__(16) float g_fch[NB*NC];
__device__ __align__(16) float g_fsa[NB*NH*NW];
__device__ __align__(16) float g_sh[NB*NC*NH];
__device__ __align__(16) float g_sw[NB*NC*NW];

// Pass 1: one block per (b, chunk of 8 channels). Full double-buffer (whole
// next channel in flight = 8 loads/thread) AND 4 CTAs/SM: registers trimmed
// via hoisted base pointers + 32-bit index math.
__global__ __launch_bounds__(256, 4) void k_reduce(const float* __restrict__ x) {
    int b = blockIdx.y, chunk = blockIdx.x, t = threadIdx.x;
    int lane = t & 31, warp = t >> 5;
    __shared__ float s_row[8][1024];     // 32KB: per-thread-quarter row partials
    __shared__ float4 s_col[8][8][16];   // 16KB: [ci][warp][wquad]
    float4 ch[4];                        // cross-channel pixel sums per quarter
#pragma unroll
    for (int i = 0; i < 4; i++) ch[i] = make_float4(0.f, 0.f, 0.f, 0.f);

    const float4* base = (const float4*)x + ((size_t)b * NC + chunk * 8) * 1024 + t;
    float* gxh = g_xh + ((size_t)b * NC + chunk * 8) * NH;
    float4 buf[2][4];
#pragma unroll
    for (int i = 0; i < 4; i++) buf[0][i] = __ldcg(base + i * 256);

#pragma unroll
    for (int ci = 0; ci < 8; ci++) {
        int cur = ci & 1;
        if (ci < 7) {
#pragma unroll
            for (int i = 0; i < 4; i++)
                buf[cur ^ 1][i] = __ldcg(base + (ci + 1) * 1024 + i * 256);
        }
        float4 ca = make_float4(0.f, 0.f, 0.f, 0.f);
#pragma unroll
        for (int i = 0; i < 4; i++) {
            float4 v = buf[cur][i];
            ch[i].x += v.x; ch[i].y += v.y; ch[i].z += v.z; ch[i].w += v.w;
            ca.x += v.x; ca.y += v.y; ca.z += v.z; ca.w += v.w;
            float rs = (v.x + v.y) + (v.z + v.w);
            int q = i * 256 + t;
            // logical (row=q>>4, col=q&15) stored swizzled: col ^ (row&15)
            s_row[ci][(q & 0x3F0) | ((q ^ (q >> 4)) & 15)] = rs;
        }
        // fold the two 16-lane halves (4 independent SHFLs, no chain)
        ca.x += __shfl_xor_sync(0xffffffffu, ca.x, 16);
        ca.y += __shfl_xor_sync(0xffffffffu, ca.y, 16);
        ca.z += __shfl_xor_sync(0xffffffffu, ca.z, 16);
        ca.w += __shfl_xor_sync(0xffffffffu, ca.w, 16);
        if (lane < 16) s_col[ci][warp][lane] = ca;
    }
    __syncthreads();

    // Tail A: row sums — 512 (ci,row) pairs, 2 per thread, swizzled reads
#pragma unroll
    for (int r2 = 0; r2 < 2; r2++) {
        int p = r2 * 256 + t;
        int ci = p >> 6, row = p & 63;
        const float* sr = s_row[ci] + row * 16;
        float s = 0.f;
#pragma unroll
        for (int k = 0; k < 16; k++) s += sr[(k ^ row) & 15];
        gxh[ci * NH + row] = s * (1.f / NW);
    }

    // Tail B: column sums + pooled — threads 0..127 = (ci, wquad)
    if (t < 128) {
        int ci = t >> 4, wq = t & 15;
        float4 s = s_col[ci][0][wq];
#pragma unroll
        for (int wv = 1; wv < 8; wv++) {
            float4 p = s_col[ci][wv][wq];
            s.x += p.x; s.y += p.y; s.z += p.z; s.w += p.w;
        }
        int c = chunk * 8 + ci;
        ((float4*)g_xw)[((size_t)b * NC + c) * 16 + wq] =
            make_float4(s.x * (1.f / NH), s.y * (1.f / NH),
                        s.z * (1.f / NH), s.w * (1.f / NH));
        float tot = s.x + s.y + s.z + s.w;       // reduce the 16 wq lanes
        tot += __shfl_xor_sync(0xffffffffu, tot, 8);
        tot += __shfl_xor_sync(0xffffffffu, tot, 4);
        tot += __shfl_xor_sync(0xffffffffu, tot, 2);
        tot += __shfl_xor_sync(0xffffffffu, tot, 1);
        if (wq == 0) g_pooled[b * NC + c] = tot * (1.f / (NH * NW));
    }

    // channel-partial store (plain float4, no atomics; stays L2-resident for k_mid)
    float4* pp = (float4*)g_part + ((size_t)b * 32 + chunk) * 1024 + t;
#pragma unroll
    for (int i = 0; i < 4; i++) pp[i * 256] = ch[i];
}

// Fused middle kernel, 128 threads:
//  blocks [0,128):   attention MLP, block = (b, l-group of 32)
//  blocks [128,384): f_sa — sum 32 chunk-partials (w/ halo rows) + 3x3 conv + sigmoid
//  blocks [384,416): f_ch — 5-tap conv over pooled channels, one block per b
__global__ __launch_bounds__(128) void k_mid(
    const float* __restrict__ w10, const float* __restrict__ w11,
    const float* __restrict__ gamma, const float* __restrict__ beta,
    const float* __restrict__ mean, const float* __restrict__ var,
    const float* __restrict__ w20, const float* __restrict__ w21) {
    int bx = blockIdx.x, t = threadIdx.x;

    if (bx < 128) {
        __shared__ float s_w10t[NC * NM];  // transposed: [c][m]
        __shared__ float s_w11[NC * NM];   // [c][m]
        __shared__ float s_y[NM * 32];     // [m][lsub]
        __shared__ float s_inv[NM], s_bias[NM];
        int b = bx >> 2, lg = bx & 3;
        int lsub = t & 31, grp = t >> 5;
        int l = lg * 32 + lsub;
#pragma unroll
        for (int k = 0; k < 32; k++) {
            int idx = k * 128 + t;
            int m = idx >> 8, c = idx & 255;
            s_w10t[c * NM + m] = w10[idx];
            s_w11[idx] = w11[idx];
        }
        if (t < NM) {
            float inv = rsqrtf(var[t] + EPSV) * gamma[t];
            s_inv[t] = inv;
            s_bias[t] = beta[t] - mean[t] * inv;
        }
        __syncthreads();

        const float* catp = (l < 64) ? g_xh + (size_t)b * NC * 64 + l
                                     : g_xw + (size_t)b * NC * 64 + (l - 64);
        float a0 = 0.f, a1 = 0.f, a2 = 0.f, a3 = 0.f;
#pragma unroll 16
        for (int c = 0; c < NC; c++) {
            float cv = __ldg(catp + (size_t)c * 64);
            float4 wv = *(const float4*)&s_w10t[c * NM + grp * 4];
            a0 = fmaf(wv.x, cv, a0);
            a1 = fmaf(wv.y, cv, a1);
            a2 = fmaf(wv.z, cv, a2);
            a3 = fmaf(wv.w, cv, a3);
        }
        int m0 = grp * 4;
        s_y[(m0 + 0) * 32 + lsub] = fmaxf(fmaf(a0, s_inv[m0 + 0], s_bias[m0 + 0]), 0.f);
        s_y[(m0 + 1) * 32 + lsub] = fmaxf(fmaf(a1, s_inv[m0 + 1], s_bias[m0 + 1]), 0.f);
        s_y[(m0 + 2) * 32 + lsub] = fmaxf(fmaf(a2, s_inv[m0 + 2], s_bias[m0 + 2]), 0.f);
        s_y[(m0 + 3) * 32 + lsub] = fmaxf(fmaf(a3, s_inv[m0 + 3], s_bias[m0 + 3]), 0.f);
        __syncthreads();

        float yr[NM];
#pragma unroll
        for (int m = 0; m < NM; m++) yr[m] = s_y[m * 32 + lsub];
        float* dst = (l < 64) ? g_sh + (size_t)b * NC * 64 + l
                              : g_sw + (size_t)b * NC * 64 + (l - 64);
#pragma unroll 4
        for (int it = 0; it < 64; it++) {
            int c = it * 4 + grp;
            const float4* wr = (const float4*)&s_w11[c * NM];
            float4 w0 = wr[0], w1 = wr[1], w2 = wr[2], w3 = wr[3];
            float ae = 0.f, ao = 0.f;                 // dual chains
            ae = fmaf(w0.x, yr[0], ae);  ao = fmaf(w0.y, yr[1], ao);
            ae = fmaf(w0.z, yr[2], ae);  ao = fmaf(w0.w, yr[3], ao);
            ae = fmaf(w1.x, yr[4], ae);  ao = fmaf(w1.y, yr[5], ao);
            ae = fmaf(w1.z, yr[6], ae);  ao = fmaf(w1.w, yr[7], ao);
            ae = fmaf(w2.x, yr[8], ae);  ao = fmaf(w2.y, yr[9], ao);
            ae = fmaf(w2.z, yr[10], ae); ao = fmaf(w2.w, yr[11], ao);
            ae = fmaf(w3.x, yr[12], ae); ao = fmaf(w3.y, yr[13], ao);
            ae = fmaf(w3.z, yr[14], ae); ao = fmaf(w3.w, yr[15], ao);
            float a = ae + ao;
            dst[(size_t)c * 64] = 1.f / (1.f + __expf(-a));
        }
    } else if (bx < 384) {
        // f_sa tile: 8 output rows per block, halo rows h0-1..h0+8 in smem
        __shared__ __align__(16) float s_m[10][64];
        int idx = bx - 128;
        int b = idx >> 3, tile = idx & 7;
        int h0 = tile * 8;
        const float4* pb = (const float4*)g_part + (size_t)b * 32 * 1024;
        // fill 10 rows x 16 quads = 160 quads, summing 32 chunk-partials each
        for (int qi = t; qi < 160; qi += 128) {
            int lr = qi >> 4, wq = qi & 15;
            int hh = h0 - 1 + lr;
            float4 acc = make_float4(0.f, 0.f, 0.f, 0.f);
            if (hh >= 0 && hh < NH) {
                int poff = hh * 16 + wq;
#pragma unroll 8
                for (int ck = 0; ck < 32; ck++) {
                    float4 v = __ldg(pb + ck * 1024 + poff);
                    acc.x += v.x; acc.y += v.y; acc.z += v.z; acc.w += v.w;
                }
            }
            *(float4*)&s_m[lr][wq * 4] =
                make_float4(acc.x * (1.f / NC), acc.y * (1.f / NC),
                            acc.z * (1.f / NC), acc.w * (1.f / NC));
        }
        float kk[9];
#pragma unroll
        for (int i = 0; i < 9; i++) kk[i] = w21[i];
        __syncthreads();
        // conv: 128 quads = 8 rows x 16 quads
        int lr = (t >> 4) + 1;         // smem row for output row h0 + (t>>4)
        int w0 = (t & 15) * 4;
        float4 o;
        float* op = (float*)&o;
#pragma unroll
        for (int j = 0; j < 4; j++) {
            int w = w0 + j;
            float acc = 0.f;
#pragma unroll
            for (int dh = -1; dh <= 1; dh++) {
#pragma unroll
                for (int dw = -1; dw <= 1; dw++) {
                    int ww = w + dw;
                    if (ww >= 0 && ww < NW)
                        acc += s_m[lr + dh][ww] * kk[(dh + 1) * 3 + (dw + 1)];
                }
            }
            op[j] = 1.f / (1.f + __expf(-acc));
        }
        ((float4*)g_fsa)[(size_t)b * 1024 + (h0 + (t >> 4)) * 16 + (t & 15)] = o;
    } else {
        // f_ch: 5-tap SAME conv over pooled channels, block per b
        int b = bx - 384;
#pragma unroll
        for (int r = 0; r < 2; r++) {
            int cc = r * 128 + t;
            float acc = 0.f;
#pragma unroll
            for (int k = 0; k < 5; k++) {
                int c2 = cc + k - 2;
                if (c2 >= 0 && c2 < NC)
                    acc += __ldg(&g_pooled[b * NC + c2]) * w20[k];
            }
            g_fch[b * NC + cc] = acc;
        }
    }
}

// Pass 2: out = x * (f_ch + s_h*s_w + f_sa). One block per (b, 4-channel group)
// — f_sa float4 loaded once per pixel for 4 planes. Block mapping REVERSED vs
// pass 1's read order (L2 telescoping); __ldcg keeps x resident for the next
// graph replay's forward pass.
__global__ __launch_bounds__(256) void k_final(const float* __restrict__ x,
                                               float* __restrict__ out) {
    int b = NB - 1 - (int)blockIdx.y;
    int cg = NC / 4 - 1 - (int)blockIdx.x;
    int t = threadIdx.x;
    int bc0 = b * NC + cg * 4;
    __shared__ __align__(16) float s_sh[4][64];
    __shared__ __align__(16) float s_sw[4][64];
#pragma unroll
    for (int j = 0; j < 2; j++) {
        int p = j * 256 + t;
        int cc = p >> 6, hh = p & 63;
        if (cc < 4) s_sh[cc][hh] = g_sh[(size_t)(bc0 + cc) * 64 + hh];
        else        s_sw[cc - 4][hh] = g_sw[(size_t)(bc0 + cc - 4) * 64 + hh];
    }
    float fch[4];
#pragma unroll
    for (int c = 0; c < 4; c++) fch[c] = g_fch[bc0 + c];
    __syncthreads();
    const float4* xp = (const float4*)x + (size_t)bc0 * 1024;
    float4* op = (float4*)out + (size_t)bc0 * 1024;
    const float4* fp = (const float4*)g_fsa + (size_t)b * 1024;
#pragma unroll
    for (int i = 0; i < 4; i++) {
        int q = i * 256 + t;
        float4 fv = __ldg(fp + q);
        int r = q >> 4;
        float4 xv[4];
#pragma unroll
        for (int c = 0; c < 4; c++) xv[c] = __ldcg(xp + c * 1024 + q);
#pragma unroll
        for (int c = 0; c < 4; c++) {
            float sh = s_sh[c][r];
            float4 swv = ((const float4*)s_sw[c])[q & 15];
            float4 o;
            o.x = xv[c].x * (fch[c] + sh * swv.x + fv.x);
            o.y = xv[c].y * (fch[c] + sh * swv.y + fv.y);
            o.z = xv[c].z * (fch[c] + sh * swv.z + fv.z);
            o.w = xv[c].w * (fch[c] + sh * swv.w + fv.w);
            __stcs(op + c * 1024 + q, o);
        }
    }
}

extern "C" void kernel_launch(void* const* d_in, const int* in_sizes, int n_in,
                              void* d_out, int out_size) {
    const float* x     = (const float*)d_in[0];
    const float* w10   = (const float*)d_in[1];
    const float* w11   = (const float*)d_in[2];
    const float* gamma = (const float*)d_in[3];
    const float* beta  = (const float*)d_in[4];
    const float* mean  = (const float*)d_in[5];
    const float* var   = (const float*)d_in[6];
    const float* w20   = (const float*)d_in[7];
    const float* w21   = (const float*)d_in[8];
    float* out = (float*)d_out;

    k_reduce<<<dim3(32, NB), 256>>>(x);
    k_mid<<<416, 128>>>(w10, w11, gamma, beta, mean, var, w20, w21);
    k_final<<<dim3(NC / 4, NB), 256>>>(x, out);
}